// round 17
// baseline (speedup 1.0000x reference)
#include <cuda_runtime.h>
#include <cuda_fp16.h>
#include <mma.h>
#include <math_constants.h>
#include <cstdint>

using namespace nvcuda;

#define S_LEN 4096
#define DIM   2048
#define HEADS 16
#define HD    128
#define GK    2048
#define BM    128
#define BN    128
#define BKC   64
#define NKC   (GK / BKC)    // 32
#define FSLD  72            // gemm smem row stride (fp16)

// ---------------- scratch (allocation-free rule: __device__ globals) ----------
__device__ __half g_Q16[HEADS * S_LEN * HD];   // pre-scaled by QKSCALE*log2e
__device__ __half g_K16[HEADS * S_LEN * HD];
__device__ __half g_V16[HEADS * S_LEN * HD];
__device__ __half g_O16[S_LEN * DIM];
__device__ __half g_X16[S_LEN * DIM];
__device__ __half g_W16[4][DIM * DIM];

// ---------------- helpers ------------------------------------------------------
__device__ __forceinline__ uint32_t smem_u32(const void* p) {
    uint32_t a;
    asm("{ .reg .u64 t; cvta.to.shared.u64 t, %1; cvt.u32.u64 %0, t; }"
        : "=r"(a) : "l"(p));
    return a;
}
#define CP_ASYNC16(dst_u32, src_ptr) \
    asm volatile("cp.async.cg.shared.global [%0], [%1], 16;" \
        :: "r"(dst_u32), "l"(src_ptr) : "memory")
#define CP_ASYNC_COMMIT() asm volatile("cp.async.commit_group;" ::: "memory")
#define CP_ASYNC_WAIT0()  asm volatile("cp.async.wait_group 0;" ::: "memory")
#define CP_ASYNC_WAIT1()  asm volatile("cp.async.wait_group 1;" ::: "memory")

__device__ __forceinline__ uint32_t pack_h2(__half a, __half b) {
    __half2 t = __halves2half2(a, b);
    return *(uint32_t*)&t;
}

#define LDSM_X4(r0, r1, r2, r3, addr) \
    asm volatile("ldmatrix.sync.aligned.m8n8.x4.shared.b16 {%0,%1,%2,%3}, [%4];" \
        : "=r"(r0), "=r"(r1), "=r"(r2), "=r"(r3) : "r"(addr))
#define LDSM_X4_T(r0, r1, r2, r3, addr) \
    asm volatile("ldmatrix.sync.aligned.m8n8.x4.trans.shared.b16 {%0,%1,%2,%3}, [%4];" \
        : "=r"(r0), "=r"(r1), "=r"(r2), "=r"(r3) : "r"(addr))
#define MMA16816(c, a0, a1, a2, a3, b0, b1) \
    asm volatile("mma.sync.aligned.m16n8k16.row.col.f32.f16.f16.f32 " \
        "{%0,%1,%2,%3}, {%4,%5,%6,%7}, {%8,%9}, {%0,%1,%2,%3};" \
        : "+f"((c)[0]), "+f"((c)[1]), "+f"((c)[2]), "+f"((c)[3]) \
        : "r"(a0), "r"(a1), "r"(a2), "r"(a3), "r"(b0), "r"(b1))

// ============================================================================
// fused 5-way split: slice 0 = X (2 chunks/thread), slices 1..4 = weights
// ============================================================================
__global__ void split_all(const float4* __restrict__ X,
                          const float4* __restrict__ s1,
                          const float4* __restrict__ s2,
                          const float4* __restrict__ s3,
                          const float4* __restrict__ s4,
                          uint2* __restrict__ dX, uint2* __restrict__ dW,
                          int nW4) {
    int i = blockIdx.x * 256 + threadIdx.x;
    if (i >= nW4) return;
    if (blockIdx.y == 0) {
        #pragma unroll
        for (int r = 0; r < 2; r++) {
            int ii = i + r * nW4;
            float4 v = X[ii];
            uint2 ho;
            ho.x = pack_h2(__float2half(v.x), __float2half(v.y));
            ho.y = pack_h2(__float2half(v.z), __float2half(v.w));
            dX[ii] = ho;
        }
    } else {
        const float4* srcs[4] = {s1, s2, s3, s4};
        float4 v = srcs[blockIdx.y - 1][i];
        uint2 ho;
        ho.x = pack_h2(__float2half(v.x), __float2half(v.y));
        ho.y = pack_h2(__float2half(v.z), __float2half(v.w));
        dW[(size_t)(blockIdx.y - 1) * nW4 + i] = ho;
    }
}

// ============================================================================
// fp16 WMMA GEMM (1-term): C = (A * B^T + bias) * scale   — 2 CTAs/SM
// ============================================================================
#define FTILE_ELEMS (128 * FSLD)
#define FTILE_BYTES (FTILE_ELEMS * 2)          // 18432
#define GEMM_SMEM   (2 * 2 * FTILE_BYTES)      // 73728

template <int MODE, int NFUSE>
__global__ __launch_bounds__(256, 2) void gemm_f16(
    const __half* __restrict__ A,
    const __half* __restrict__ B0, const __half* __restrict__ B1,
    const __half* __restrict__ B2,
    const float* __restrict__ bias0, const float* __restrict__ bias1,
    const float* __restrict__ bias2,
    float sc0, float sc1, float sc2,
    float* __restrict__ C,
    __half* __restrict__ Ch0, __half* __restrict__ Ch1,
    __half* __restrict__ Ch2,
    int M, int N)
{
    extern __shared__ char smemg[];
    __half* sbuf = (__half*)smemg;
    const uint32_t sb = smem_u32(smemg);

    const __half* B    = B0;
    const float*  bias = bias0;
    __half*       Ch   = Ch0;
    float         sc   = sc0;
    if (NFUSE > 1) {
        if (blockIdx.z == 1) { B = B1; bias = bias1; Ch = Ch1; sc = sc1; }
        else if (blockIdx.z == 2) { B = B2; bias = bias2; Ch = Ch2; sc = sc2; }
    }

    const int tid  = threadIdx.x;
    const int wid  = tid >> 5;
    const int m0   = blockIdx.y * BM;
    const int n0   = blockIdx.x * BN;
    const int wm   = (wid & 3) * 32;
    const int wn   = (wid >> 2) * 64;

    const __half* srcA = A + (size_t)m0 * GK;
    const __half* srcB = B + (size_t)n0 * GK;

    const int lrow0 = tid >> 3;
    const int lc16  = (tid & 7) * 8;

    auto load_chunk = [&](int kt, int buf) {
        const int kc = kt * BKC;
        const __half* ga = srcA + (size_t)lrow0 * GK + kc + lc16;
        const __half* gb = srcB + (size_t)lrow0 * GK + kc + lc16;
        uint32_t da = sb + buf * (2 * FTILE_BYTES) + (lrow0 * FSLD + lc16) * 2;
        uint32_t db = da + FTILE_BYTES;
        #pragma unroll
        for (int i = 0; i < 4; i++) {
            CP_ASYNC16(da + i * (32 * FSLD * 2), ga + (size_t)(i * 32) * GK);
            CP_ASYNC16(db + i * (32 * FSLD * 2), gb + (size_t)(i * 32) * GK);
        }
    };

    wmma::fragment<wmma::accumulator, 16, 16, 16, float> acc[2][4];
    #pragma unroll
    for (int t = 0; t < 2; t++)
        #pragma unroll
        for (int u = 0; u < 4; u++) wmma::fill_fragment(acc[t][u], 0.0f);

    load_chunk(0, 0);
    CP_ASYNC_COMMIT();
    CP_ASYNC_WAIT0();
    __syncthreads();

    for (int kt = 0; kt < NKC; kt++) {
        const int cur = kt & 1;
        if (kt + 1 < NKC) {
            load_chunk(kt + 1, cur ^ 1);
            CP_ASYNC_COMMIT();
        }

        const __half* pA = sbuf + cur * (2 * FTILE_ELEMS);
        const __half* pB = pA + FTILE_ELEMS;

        #pragma unroll
        for (int ks = 0; ks < 4; ks++) {
            wmma::fragment<wmma::matrix_a, 16, 16, 16, __half, wmma::row_major> ah[2];
            wmma::fragment<wmma::matrix_b, 16, 16, 16, __half, wmma::col_major> bh[4];
            #pragma unroll
            for (int t = 0; t < 2; t++)
                wmma::load_matrix_sync(ah[t], pA + (wm + t * 16) * FSLD + ks * 16, FSLD);
            #pragma unroll
            for (int u = 0; u < 4; u++)
                wmma::load_matrix_sync(bh[u], pB + (wn + u * 16) * FSLD + ks * 16, FSLD);
            #pragma unroll
            for (int t = 0; t < 2; t++)
                #pragma unroll
                for (int u = 0; u < 4; u++)
                    wmma::mma_sync(acc[t][u], ah[t], bh[u], acc[t][u]);
        }

        if (kt + 1 < NKC) CP_ASYNC_WAIT0();
        __syncthreads();
    }

    float* sC = (float*)smemg;
    const int CLD = 132;
    #pragma unroll
    for (int t = 0; t < 2; t++)
        #pragma unroll
        for (int u = 0; u < 4; u++)
            wmma::store_matrix_sync(sC + (wm + t * 16) * CLD + wn + u * 16,
                                    acc[t][u], CLD, wmma::mem_row_major);
    __syncthreads();

    #pragma unroll
    for (int i = 0; i < 16; i++) {
        const int flat4 = tid + i * 256;
        const int row = flat4 >> 5;
        const int c   = (flat4 & 31) * 4;
        float v0 = (sC[row * CLD + c + 0] + bias[n0 + c + 0]) * sc;
        float v1 = (sC[row * CLD + c + 1] + bias[n0 + c + 1]) * sc;
        float v2 = (sC[row * CLD + c + 2] + bias[n0 + c + 2]) * sc;
        float v3 = (sC[row * CLD + c + 3] + bias[n0 + c + 3]) * sc;
        if (MODE == 0) {
            *(float4*)(C + (size_t)(m0 + row) * N + n0 + c) =
                make_float4(v0, v1, v2, v3);
        } else {
            size_t idx = (size_t)blockIdx.x * (size_t)M * 128 + (size_t)(m0 + row) * 128 + c;
            uint2 ho;
            ho.x = pack_h2(__float2half(v0), __float2half(v1));
            ho.y = pack_h2(__float2half(v2), __float2half(v3));
            *(uint2*)(Ch + idx) = ho;
        }
    }
}

// ============================================================================
// Flash attention (causal) — register-resident softmax (raw mma.m16n8k16).
// Warp w owns rows [w*16, w*16+16) x ALL 64 keys: softmax fully warp-local.
// S accumulator frags are converted in-register to P A-operand frags (FA2).
// SMEM: Q [128][136]h @0 (34816); KV bufs [64][136]h @34816+b*17408.
// Total 69632 B; 2 CTAs/SM.
// ============================================================================
#define AQ_OFF  0
#define AKV_OFF 34816
#define KVBUF   17408
#define ATTN_SMEM 69632

__global__ __launch_bounds__(256, 2) void flash_attn_f16(
    const __half* __restrict__ Q16, const __half* __restrict__ K16,
    const __half* __restrict__ V16,
    __half* __restrict__ O16)
{
    extern __shared__ char smem[];
    const uint32_t sb = smem_u32(smem);

    const int tid  = threadIdx.x;
    const int wid  = tid >> 5;
    const int lane = tid & 31;
    const int g    = lane >> 2;
    const int t4   = lane & 3;
    const int wq   = wid * 16;
    const int qt   = gridDim.x - 1 - blockIdx.x;   // heavy CTAs first
    const int h    = blockIdx.y;
    const int ntiles = 2 * (qt + 1);

    const __half* Qh = Q16 + ((size_t)h * S_LEN + (size_t)qt * 128) * HD;
    const __half* Kh = K16 + (size_t)h * S_LEN * HD;
    const __half* Vh = V16 + (size_t)h * S_LEN * HD;

    auto loadQ = [&]() {
        #pragma unroll
        for (int rep = 0; rep < 8; rep++) {
            int id  = tid + rep * 256;
            int row = id >> 4, cc = (id & 15) * 8;
            CP_ASYNC16(sb + AQ_OFF + (row * 136 + cc) * 2, Qh + (size_t)row * HD + cc);
        }
    };
    auto loadKV = [&](const __half* Tp, int ktile, int buf) {
        const size_t base = (size_t)ktile * 64 * HD;
        #pragma unroll
        for (int rep = 0; rep < 4; rep++) {
            int id  = tid + rep * 256;
            int row = id >> 4, cc = (id & 15) * 8;
            CP_ASYNC16(sb + AKV_OFF + buf * KVBUF + (row * 136 + cc) * 2,
                       Tp + base + (size_t)row * HD + cc);
        }
    };

    loadQ();
    loadKV(Kh, 0, 0);
    CP_ASYNC_COMMIT();

    // O accumulator: 16 n-blocks (128 d) x 4 floats, m16n8 C layout
    float facc[16][4];
    #pragma unroll
    for (int j = 0; j < 16; j++)
        #pragma unroll
        for (int e = 0; e < 4; e++) facc[j][e] = 0.0f;
    float M0 = -30000.0f, M1 = -30000.0f;   // running row maxima (rows g, g+8)
    float l0 = 0.0f, l1 = 0.0f;

    // ldmatrix address components (in halves, x2 for bytes)
    const uint32_t qaddr0 = sb + AQ_OFF +
        (((wq + (lane & 15)) * 136 + ((lane & 16) >> 1)) * 2);
    const int krow = (lane & 7) + ((lane >> 4) << 3);   // key row within pair blk
    const int vrow = (lane & 15);
    const int row0 = qt * 128 + wq + g;

    for (int kt = 0; kt < ntiles; kt++) {
        const int cur = kt & 1;
        const uint32_t kvb = sb + AKV_OFF + cur * KVBUF;

        CP_ASYNC_WAIT0();
        __syncthreads();                 // K(kt) visible; V(kt-1) reads done

        // ---- S = Q' K^T : 8 n-blocks (64 keys), regs only ----
        float cs[8][4];
        #pragma unroll
        for (int j = 0; j < 8; j++)
            #pragma unroll
            for (int e = 0; e < 4; e++) cs[j][e] = 0.0f;

        #pragma unroll
        for (int kb = 0; kb < 8; kb++) {
            uint32_t a0, a1, a2, a3;
            LDSM_X4(a0, a1, a2, a3, qaddr0 + kb * 32);
            #pragma unroll
            for (int jp = 0; jp < 4; jp++) {
                uint32_t b0, b1, b2, b3;
                uint32_t ka = kvb + (((jp * 16 + krow) * 136
                                      + kb * 16 + (lane & 8)) * 2);
                LDSM_X4(b0, b1, b2, b3, ka);
                MMA16816(cs[2 * jp],     a0, a1, a2, a3, b0, b1);
                MMA16816(cs[2 * jp + 1], a0, a1, a2, a3, b2, b3);
            }
        }
        __syncthreads();                 // all warps done reading K(kt)

        // ---- prefetch: V(kt) overwrites K(kt); K(kt+1) -> other buf ----
        loadKV(Vh, kt, cur);
        CP_ASYNC_COMMIT();
        if (kt + 1 < ntiles) loadKV(Kh, kt + 1, cur ^ 1);
        CP_ASYNC_COMMIT();

        // ---- causal mask (register) ----
        if (kt >= 2 * qt) {
            #pragma unroll
            for (int j = 0; j < 8; j++) {
                const int colb = kt * 64 + 8 * j + 2 * t4;
                if (colb     > row0)     cs[j][0] = -30000.0f;
                if (colb + 1 > row0)     cs[j][1] = -30000.0f;
                if (colb     > row0 + 8) cs[j][2] = -30000.0f;
                if (colb + 1 > row0 + 8) cs[j][3] = -30000.0f;
            }
        }

        // ---- per-row max (quad shfl), online update ----
        float mx0 = -30000.0f, mx1 = -30000.0f;
        #pragma unroll
        for (int j = 0; j < 8; j++) {
            mx0 = fmaxf(mx0, fmaxf(cs[j][0], cs[j][1]));
            mx1 = fmaxf(mx1, fmaxf(cs[j][2], cs[j][3]));
        }
        mx0 = fmaxf(mx0, __shfl_xor_sync(0xffffffffu, mx0, 1));
        mx0 = fmaxf(mx0, __shfl_xor_sync(0xffffffffu, mx0, 2));
        mx1 = fmaxf(mx1, __shfl_xor_sync(0xffffffffu, mx1, 1));
        mx1 = fmaxf(mx1, __shfl_xor_sync(0xffffffffu, mx1, 2));
        const float M0n = fmaxf(M0, mx0);
        const float M1n = fmaxf(M1, mx1);
        const float cr0 = exp2f(M0 - M0n);
        const float cr1 = exp2f(M1 - M1n);
        M0 = M0n; M1 = M1n;

        // ---- exp (f16x2) + pack directly into PV A-operand frags ----
        uint32_t P[4][4];
        float ps0 = 0.0f, ps1 = 0.0f;
        #pragma unroll
        for (int j = 0; j < 8; j++) {
            __half2 x0 = __floats2half2_rn(cs[j][0] - M0n, cs[j][1] - M0n);
            __half2 x1 = __floats2half2_rn(cs[j][2] - M1n, cs[j][3] - M1n);
            uint32_t e0, e1;
            asm("ex2.approx.f16x2 %0, %1;" : "=r"(e0) : "r"(*(uint32_t*)&x0));
            asm("ex2.approx.f16x2 %0, %1;" : "=r"(e1) : "r"(*(uint32_t*)&x1));
            float2 f0 = __half22float2(*(__half2*)&e0);
            float2 f1 = __half22float2(*(__half2*)&e1);
            ps0 += f0.x + f0.y;
            ps1 += f1.x + f1.y;
            const int m = j >> 1;
            if ((j & 1) == 0) { P[m][0] = e0; P[m][1] = e1; }
            else              { P[m][2] = e0; P[m][3] = e1; }
        }
        ps0 += __shfl_xor_sync(0xffffffffu, ps0, 1);
        ps0 += __shfl_xor_sync(0xffffffffu, ps0, 2);
        ps1 += __shfl_xor_sync(0xffffffffu, ps1, 1);
        ps1 += __shfl_xor_sync(0xffffffffu, ps1, 2);
        l0 = l0 * cr0 + ps0;
        l1 = l1 * cr1 + ps1;

        // ---- rescale O accumulators by per-row corr ----
        #pragma unroll
        for (int j = 0; j < 16; j++) {
            facc[j][0] *= cr0;  facc[j][1] *= cr0;
            facc[j][2] *= cr1;  facc[j][3] *= cr1;
        }

        CP_ASYNC_WAIT1();               // V(kt) arrived (K(kt+1) may fly)
        __syncthreads();                // V visible to all warps

        // ---- O += P V : 4 key-blocks x 16 d n-blocks ----
        #pragma unroll
        for (int m = 0; m < 4; m++) {
            #pragma unroll
            for (int jp = 0; jp < 8; jp++) {
                uint32_t b0, b1, b2, b3;
                uint32_t va = kvb + (((m * 16 + vrow) * 136
                                      + jp * 16 + ((lane & 16) >> 1)) * 2);
                LDSM_X4_T(b0, b1, b2, b3, va);
                MMA16816(facc[2 * jp],     P[m][0], P[m][1], P[m][2], P[m][3], b0, b1);
                MMA16816(facc[2 * jp + 1], P[m][0], P[m][1], P[m][2], P[m][3], b2, b3);
            }
        }
    }

    // ---- epilogue: O = facc / l, fp16, direct global stores ----
    const float i0 = 1.0f / l0;
    const float i1 = 1.0f / l1;
    const size_t rb0 = (size_t)row0 * DIM + (size_t)h * HD + 2 * t4;
    const size_t rb1 = rb0 + 8 * (size_t)DIM;
    #pragma unroll
    for (int j = 0; j < 16; j++) {
        *(uint32_t*)(O16 + rb0 + 8 * j) =
            pack_h2(__float2half(facc[j][0] * i0), __float2half(facc[j][1] * i0));
        *(uint32_t*)(O16 + rb1 + 8 * j) =
            pack_h2(__float2half(facc[j][2] * i1), __float2half(facc[j][3] * i1));
    }
}

// ============================================================================
// launch
// ============================================================================
extern "C" void kernel_launch(void* const* d_in, const int* in_sizes, int n_in,
                              void* d_out, int out_size)
{
    const float* X  = (const float*)d_in[0];
    const float* Wq = (const float*)d_in[1];
    const float* bq = (const float*)d_in[2];
    const float* Wk = (const float*)d_in[3];
    const float* bk = (const float*)d_in[4];
    const float* Wv = (const float*)d_in[5];
    const float* bv = (const float*)d_in[6];
    const float* Wo = (const float*)d_in[7];
    const float* bo = (const float*)d_in[8];

    __half *Q16, *K16, *V16, *O16, *X16, *W16;
    cudaGetSymbolAddress((void**)&Q16, g_Q16);
    cudaGetSymbolAddress((void**)&K16, g_K16);
    cudaGetSymbolAddress((void**)&V16, g_V16);
    cudaGetSymbolAddress((void**)&O16, g_O16);
    cudaGetSymbolAddress((void**)&X16, g_X16);
    cudaGetSymbolAddress((void**)&W16, g_W16);

    const int NW4 = DIM * DIM / 4;

    dim3 gS((NW4 + 255) / 256, 5);
    split_all<<<gS, 256>>>((const float4*)X,
                           (const float4*)Wq, (const float4*)Wk,
                           (const float4*)Wv, (const float4*)Wo,
                           (uint2*)X16, (uint2*)W16, NW4);

    cudaFuncSetAttribute(gemm_f16<1, 3>,
        cudaFuncAttributeMaxDynamicSharedMemorySize, GEMM_SMEM);
    cudaFuncSetAttribute(gemm_f16<0, 1>,
        cudaFuncAttributeMaxDynamicSharedMemorySize, GEMM_SMEM);
    cudaFuncSetAttribute(flash_attn_f16,
        cudaFuncAttributeMaxDynamicSharedMemorySize, ATTN_SMEM);

    // Q pre-scale: (1/sqrt(128)) * log2(e)
    const float QSC = 0.08838834764831843f * 1.4426950408889634f;

    dim3 gQKV(DIM / BN, S_LEN / BM, 3);
    gemm_f16<1, 3><<<gQKV, 256, GEMM_SMEM>>>(X16,
        W16 + 0 * (size_t)DIM * DIM, W16 + 1 * (size_t)DIM * DIM,
        W16 + 2 * (size_t)DIM * DIM,
        bq, bk, bv, QSC, 1.0f, 1.0f, nullptr, Q16, K16, V16, S_LEN, DIM);

    dim3 gAttn(S_LEN / 128, HEADS);
    flash_attn_f16<<<gAttn, 256, ATTN_SMEM>>>(Q16, K16, V16, O16);

    dim3 gGemm(DIM / BN, S_LEN / BM);
    gemm_f16<0, 1><<<gGemm, 256, GEMM_SMEM>>>(O16,
        W16 + 3 * (size_t)DIM * DIM, nullptr, nullptr,
        bo, nullptr, nullptr, 1.0f, 1.0f, 1.0f,
        (float*)d_out, nullptr, nullptr, nullptr, S_LEN, DIM);
}